// round 14
// baseline (speedup 1.0000x reference)
#include <cuda_runtime.h>
#include <cstdint>

#define D 8192
#define B 8
#define NBLK 256                     // iter blocks: 32 j-cols (one j-tile PAIR) each
#define CPACK 2262.7417f             // 25 * sqrt(8192): pack target rms = 25

// Static device scratch (no runtime allocation allowed).
__device__ __align__(128) unsigned g_M8[(size_t)D * D / 4];  // 64 MB s8 M, pair-fragment-linear
__device__ __align__(128) unsigned g_M4[(size_t)D * D / 8];  // 32 MB s4 M (nibble-packed pairs)
__device__ __align__(16) float    g_u[2][B * D];             // ping-pong fp32 state
__device__ __align__(16) float    g_part[2][NBLK][B];        // per-block row sum(val^2)
__device__ __align__(16) unsigned g_hb8[(D / 32) * 64];      // 64 KB: h s8 B-fragments
__device__ float g_scale[B];                                 // per-row pack scale s_b
__device__ int   g_sums[2][B];                               // per-row sum of q_h (dbl-buffered)

// ---------------------------------------------------------------------------
// m16n8k32 s8 mma (s32 accumulate)
// ---------------------------------------------------------------------------
__device__ __forceinline__ void mma_s8(int* d, const uint4& a, unsigned b0, unsigned b1) {
    asm volatile(
        "mma.sync.aligned.m16n8k32.row.col.s32.s8.s8.s32 "
        "{%0,%1,%2,%3},{%4,%5,%6,%7},{%8,%9},{%0,%1,%2,%3};"
        : "+r"(d[0]), "+r"(d[1]), "+r"(d[2]), "+r"(d[3])
        : "r"(a.x), "r"(a.y), "r"(a.z), "r"(a.w), "r"(b0), "r"(b1));
}

// 256-bit A load (the .v8.b32 form ptxas requires for L2 hints)
__device__ __forceinline__ void ldg_v8_el(const unsigned* p, uint4& a, uint4& b) {
    asm volatile(
        "ld.global.nc.L2::evict_last.v8.b32 {%0,%1,%2,%3,%4,%5,%6,%7}, [%8];"
        : "=r"(a.x), "=r"(a.y), "=r"(a.z), "=r"(a.w),
          "=r"(b.x), "=r"(b.y), "=r"(b.z), "=r"(b.w) : "l"(p));
}

// sign-extend 4 packed nibbles (at low half of each byte) to 4 s8 bytes
__device__ __forceinline__ unsigned sx4(unsigned t) {
    return __vsub4(t ^ 0x08080808u, 0x08080808u);
}

// ---------------------------------------------------------------------------
// One-time: M fp32 -> s8 affine (q = rni(255*m - 127.5)), PAIR-FRAGMENT-LINEAR
// (verified R7..R13): word W(cg=i/32, jt=j/16, L, r) = cg*65536 + (jt>>1)*256
// + L*8 + (jt&1)*4 + r; one v8 load per lane feeds both j-tiles of a pair.
// ---------------------------------------------------------------------------
__global__ void convert_i8_kernel(const float* __restrict__ M) {
    __shared__ char tq[32 * 128];
    const int tid = threadIdx.x;                 // 256
    const int bi  = blockIdx.x & 255;            // i-chunk 0..255 (cg)
    const int bj  = blockIdx.x >> 8;             // j-super 0..63 (128 j each)
    const int i0  = bi * 32, j0 = bj * 128;

    const float4* M4p = (const float4*)M;
#pragma unroll
    for (int rep = 0; rep < 4; rep++) {
        int idx = rep * 256 + tid;               // 1024 float4 = 32 x 128 floats
        int r = idx >> 5, c4 = idx & 31;
        float4 v = M4p[(size_t)(i0 + r) * (D / 4) + (j0 >> 2) + c4];
        float vv[4] = {v.x, v.y, v.z, v.w};
#pragma unroll
        for (int e = 0; e < 4; e++) {
            int q = __float2int_rn(fmaf(vv[e], 255.f, -127.5f));
            q = max(-128, min(127, q));
            tq[r * 128 + c4 * 4 + e] = (char)q;
        }
    }
    __syncthreads();

#pragma unroll
    for (int wrep = 0; wrep < 4; wrep++) {
        int widx = wrep * 256 + tid;             // 1024 words per block
        int tl = widx >> 7, wi = widx & 127;     // tile-local 0..7, word-in-tile
        int Lq = wi >> 2, rq = wi & 3;
        int jloc = (Lq >> 2) + 8 * (rq & 1);
        int kb   = 4 * (Lq & 3) + 16 * (rq >> 1);
        unsigned wd = ((unsigned char)tq[(kb + 0) * 128 + tl * 16 + jloc])
                    | ((unsigned char)tq[(kb + 1) * 128 + tl * 16 + jloc] << 8)
                    | ((unsigned char)tq[(kb + 2) * 128 + tl * 16 + jloc] << 16)
                    | ((unsigned char)tq[(kb + 3) * 128 + tl * 16 + jloc] << 24);
        int jt = bj * 8 + tl;
        g_M8[(size_t)bi * 65536 + (jt >> 1) * 256 + Lq * 8 + (jt & 1) * 4 + rq] = wd;
    }
}

// ---------------------------------------------------------------------------
// One-time: g_M8 -> g_M4 (4-bit). q4 = (q8 +sat 8) >> 4 (floor), dequant
// m = (16*q4 + 127)/255. Layouts are linearly congruent:
//   g_M4[cg4*65536 + off] : lo nibbles = g_M8[(2cg4)*65536 + off] (even k32)
//                           hi nibbles = g_M8[(2cg4+1)*65536 + off] (odd k32)
// Per byte: out = ((ta>>4)&0x0F) | (tb & 0xF0), ta/tb = vaddss4(q8, 8).
// ---------------------------------------------------------------------------
__device__ __forceinline__ unsigned pack_nib(unsigned a, unsigned b) {
    unsigned ta = __vaddss4(a, 0x08080808u);
    unsigned tb = __vaddss4(b, 0x08080808u);
    return ((ta >> 4) & 0x0F0F0F0Fu) | (tb & 0xF0F0F0F0u);
}
__global__ void convert_i4_kernel() {
    size_t idx   = (size_t)blockIdx.x * 256 + threadIdx.x;   // uint4 id, 2M total
    size_t wbase = idx * 4;
    size_t cg4   = wbase >> 16;
    unsigned off = (unsigned)(wbase & 65535u);
    const uint4 A  = *(const uint4*)(g_M8 + (cg4 * 2) * 65536 + off);
    const uint4 Bv = *(const uint4*)(g_M8 + (cg4 * 2 + 1) * 65536 + off);
    uint4 o;
    o.x = pack_nib(A.x, Bv.x);
    o.y = pack_nib(A.y, Bv.y);
    o.z = pack_nib(A.z, Bv.z);
    o.w = pack_nib(A.w, Bv.w);
    *(uint4*)(g_M4 + wbase) = o;
}

// ---------------------------------------------------------------------------
// One-time: copy x -> g_u[0]; ||x_b||^2 -> g_part[0][0][b]; zero g_sums[0].
// ---------------------------------------------------------------------------
__global__ void prep_kernel(const float* __restrict__ x) {
    const int b = blockIdx.x, tid = threadIdx.x;  // 8 blocks x 256
    __shared__ float red[8];
    float ss = 0.f;
    for (int i = tid; i < D; i += 256) {
        float v = x[b * D + i];
        g_u[0][b * D + i] = v;
        ss = fmaf(v, v, ss);
    }
#pragma unroll
    for (int o = 16; o; o >>= 1) ss += __shfl_down_sync(0xFFFFFFFFu, ss, o);
    if ((tid & 31) == 0) red[tid >> 5] = ss;
    __syncthreads();
    if (tid == 0) {
        float tot = 0.f;
#pragma unroll
        for (int w = 0; w < 8; w++) tot += red[w];
        red[0] = tot;
        g_sums[0][b] = 0;
    }
    __syncthreads();
    g_part[0][tid][b] = (tid == 0) ? red[0] : 0.f;   // 256 partial slots
}

// ---------------------------------------------------------------------------
// Per-iteration pack (grid 64 = 8 rows x 8 segments, 256 threads):
// s_b = CPACK/||u_b||; quantize h -> s8 B-fragments; exact zero-point sums
// via integer atomicAdd. Word layout (verified): element i -> word
// (i>>5)*64 + b*8 + ((i>>2)&3)*2 + ((i>>4)&1), byte i&3.
// ---------------------------------------------------------------------------
__global__ void pack_kernel(int src) {
    const int b   = blockIdx.x >> 3;
    const int seg = blockIdx.x & 7;
    const int tid = threadIdx.x;                  // 256
    __shared__ float sred[8];
    __shared__ float s_sh;
    __shared__ int   ired[8];

    float ps = g_part[src][tid][b];               // 256 block-partials
#pragma unroll
    for (int o = 16; o; o >>= 1) ps += __shfl_down_sync(0xFFFFFFFFu, ps, o);
    if ((tid & 31) == 0) sred[tid >> 5] = ps;
    __syncthreads();
    if (tid == 0) {
        float t = 0.f;
#pragma unroll
        for (int w = 0; w < 8; w++) t += sred[w];
        s_sh = CPACK * rsqrtf(fmaxf(t, 1e-30f));
        if (seg == 0) g_scale[b] = s_sh;
    }
    __syncthreads();
    const float s = s_sh;

    const int i0 = seg * 1024 + tid * 4;
    float4 v = ((const float4*)(g_u[src] + (size_t)b * D))[i0 >> 2];
    float vv[4] = {v.x, v.y, v.z, v.w};
    unsigned wd = 0;
    int qsum = 0;
#pragma unroll
    for (int e = 0; e < 4; e++) {
        int q = __float2int_rn(vv[e] * s);
        q = max(-127, min(127, q));
        qsum += q;
        wd |= (unsigned)(q & 255) << (8 * e);
    }
    const int word = (i0 >> 5) * 64 + b * 8 + ((i0 >> 2) & 3) * 2 + ((i0 >> 4) & 1);
    g_hb8[word] = wd;

#pragma unroll
    for (int o = 16; o; o >>= 1) qsum += __shfl_down_sync(0xFFFFFFFFu, qsum, o);
    if ((tid & 31) == 0) ired[tid >> 5] = qsum;
    __syncthreads();
    if (tid == 0) {
        int t = 0;
#pragma unroll
        for (int w = 0; w < 8; w++) t += ired[w];
        atomicAdd(&g_sums[src][b], t);
    }
}

// ---------------------------------------------------------------------------
// s4-M step (iterations 0..12): u_next = leaky(0.5*s_b*dec + s_b*(u@M))/CPACK
//   s_b*dot_j = [ 16*Σ q_h*q4 + 127*Σ q_h ] / 255
// Grid 256 x 512 thr (16 warps): warp w covers 8 k64-chunks; per chunk:
// 1 v8 load of packed nibbles -> in-register expansion (vsub4 trick) into the
// VERIFIED s8 A-fragments -> 4 s8 mmas (lo nibbles = even k32 chunk w/ vb0,
// hi = odd w/ vb1). Halves M traffic (32 MB/step) vs the s8 path.
// ---------------------------------------------------------------------------
template <bool FIRST>
__global__ void __launch_bounds__(512, 3)
iter4_kernel(const float* __restrict__ hs_in, int src) {
    __shared__ int   redH[16 * 256];   // 16 KB split-K buffer
    __shared__ float arr_out[8];
    const int tid = threadIdx.x;
    const int L   = tid & 31;
    const int w   = tid >> 5;          // 0..15
    const int jp  = blockIdx.x;        // j-tile pair 0..255
    const int jb  = jp * 32;

    if (blockIdx.x == 0 && tid < B) g_sums[src ^ 1][tid] = 0;

    int acc0[4] = {0, 0, 0, 0};
    int acc1[4] = {0, 0, 0, 0};
    const uint2* bH = (const uint2*)g_hb8;
    const unsigned* aBase = g_M4 + (size_t)(w * 8) * 65536 + jp * 256 + L * 8;

#pragma unroll 2
    for (int c = 0; c < 8; c++) {
        const int cg4 = w * 8 + c;                       // k64-chunk
        uint2 vb0 = __ldg(&bH[(2 * cg4 + 0) * 32 + L]);
        uint2 vb1 = __ldg(&bH[(2 * cg4 + 1) * 32 + L]);
        uint4 A0, A1;
        ldg_v8_el(aBase + (size_t)c * 65536, A0, A1);

        // even k32 chunk (lo nibbles)
        {
            uint4 e = make_uint4(sx4(A0.x & 0x0F0F0F0Fu), sx4(A0.y & 0x0F0F0F0Fu),
                                 sx4(A0.z & 0x0F0F0F0Fu), sx4(A0.w & 0x0F0F0F0Fu));
            mma_s8(acc0, e, vb0.x, vb0.y);
        }
        {
            uint4 e = make_uint4(sx4(A1.x & 0x0F0F0F0Fu), sx4(A1.y & 0x0F0F0F0Fu),
                                 sx4(A1.z & 0x0F0F0F0Fu), sx4(A1.w & 0x0F0F0F0Fu));
            mma_s8(acc1, e, vb0.x, vb0.y);
        }
        // odd k32 chunk (hi nibbles)
        {
            uint4 o = make_uint4(sx4((A0.x >> 4) & 0x0F0F0F0Fu), sx4((A0.y >> 4) & 0x0F0F0F0Fu),
                                 sx4((A0.z >> 4) & 0x0F0F0F0Fu), sx4((A0.w >> 4) & 0x0F0F0F0Fu));
            mma_s8(acc0, o, vb1.x, vb1.y);
        }
        {
            uint4 o = make_uint4(sx4((A1.x >> 4) & 0x0F0F0F0Fu), sx4((A1.y >> 4) & 0x0F0F0F0Fu),
                                 sx4((A1.z >> 4) & 0x0F0F0F0Fu), sx4((A1.w >> 4) & 0x0F0F0F0Fu));
            mma_s8(acc1, o, vb1.x, vb1.y);
        }
    }

    // split-K: D-frag (j_l = (L>>2) [+8], b = 2*(L&3) [+1]); odd tile at +16
    {
        int* rw = redH + w * 256;                        // [b*32 + j_l]
        const int b0 = 2 * (L & 3);
        const int jl = L >> 2;
        rw[(b0 + 0) * 32 + jl]          = acc0[0];
        rw[(b0 + 1) * 32 + jl]          = acc0[1];
        rw[(b0 + 0) * 32 + jl + 8]      = acc0[2];
        rw[(b0 + 1) * 32 + jl + 8]      = acc0[3];
        rw[(b0 + 0) * 32 + jl + 16]     = acc1[0];
        rw[(b0 + 1) * 32 + jl + 16]     = acc1[1];
        rw[(b0 + 0) * 32 + jl + 24]     = acc1[2];
        rw[(b0 + 1) * 32 + jl + 24]     = acc1[3];
    }
    __syncthreads();

    // epilogue: 256 threads = 32 j x 8 b (warp == one b row)
    if (tid < 256) {
        const int j_l = tid & 31;
        const int b   = tid >> 5;
        int hsum = 0;
#pragma unroll
        for (int ww = 0; ww < 16; ww++) hsum += redH[ww * 256 + b * 32 + j_l];

        const float s_b = g_scale[b];
        const float dot = (16.f * (float)hsum + 127.f * (float)g_sums[src][b]) * (1.f / 255.f);

        const int j = jb + j_l;
        const float dec = FIRST ? hs_in[j] : g_u[src][(size_t)b * D + j];
        float preq = fmaf(0.5f * s_b, dec, dot);
        float val  = (preq >= 0.f) ? preq : 0.01f * preq;   // leaky (scale>0 commutes)
        val *= (1.0f / CPACK);
        g_u[src ^ 1][(size_t)b * D + j] = val;

        float v2 = val * val;                  // full warp shares one b
#pragma unroll
        for (int o = 16; o; o >>= 1) v2 += __shfl_down_sync(0xFFFFFFFFu, v2, o);
        if (L == 0) arr_out[b] = v2;
    }
    __syncthreads();
    if (tid < B)
        g_part[src ^ 1][blockIdx.x][tid] = arr_out[tid];
}

// ---------------------------------------------------------------------------
// Full-precision s8 step (iterations 13..15) — R12's verified kernel:
//   s_b*dot_j = [ Σ q_h*q_m + 127.5*Σ q_h ] / 255
// Grid 256 x 1024 thr (32 warps, 2 CTAs/SM).
// ---------------------------------------------------------------------------
__global__ void __launch_bounds__(1024, 2)
iter8_kernel(const float* __restrict__ hs_in, int src) {
    __shared__ int   redH[32 * 256];   // 32 KB split-K buffer
    __shared__ float arr_out[8];
    const int tid = threadIdx.x;
    const int L   = tid & 31;
    const int w   = tid >> 5;             // 0..31
    const int jp  = blockIdx.x;           // j-tile pair 0..255
    const int jb  = jp * 32;

    if (blockIdx.x == 0 && tid < B) g_sums[src ^ 1][tid] = 0;

    int acc0[4] = {0, 0, 0, 0};
    int acc1[4] = {0, 0, 0, 0};
    const uint2* bH = (const uint2*)g_hb8;

#pragma unroll
    for (int c = 0; c < 8; c++) {
        const int cg = w * 8 + c;                        // k32-chunk
        uint2 vb = __ldg(&bH[cg * 32 + L]);
        uint4 a0, a1;
        ldg_v8_el(g_M8 + (size_t)cg * 65536 + jp * 256 + L * 8, a0, a1);
        mma_s8(acc0, a0, vb.x, vb.y);
        mma_s8(acc1, a1, vb.x, vb.y);
    }

    {
        int* rw = redH + w * 256;                        // [b*32 + j_l]
        const int b0 = 2 * (L & 3);
        const int jl = L >> 2;
        rw[(b0 + 0) * 32 + jl]          = acc0[0];
        rw[(b0 + 1) * 32 + jl]          = acc0[1];
        rw[(b0 + 0) * 32 + jl + 8]      = acc0[2];
        rw[(b0 + 1) * 32 + jl + 8]      = acc0[3];
        rw[(b0 + 0) * 32 + jl + 16]     = acc1[0];
        rw[(b0 + 1) * 32 + jl + 16]     = acc1[1];
        rw[(b0 + 0) * 32 + jl + 24]     = acc1[2];
        rw[(b0 + 1) * 32 + jl + 24]     = acc1[3];
    }
    __syncthreads();

    if (tid < 256) {
        const int j_l = tid & 31;
        const int b   = tid >> 5;
        int hsum = 0;
#pragma unroll
        for (int ww = 0; ww < 32; ww++) hsum += redH[ww * 256 + b * 32 + j_l];

        const float s_b = g_scale[b];
        const float dot = ((float)hsum + 127.5f * (float)g_sums[src][b]) * (1.f / 255.f);

        const int j = jb + j_l;
        const float dec = g_u[src][(size_t)b * D + j];
        float preq = fmaf(0.5f * s_b, dec, dot);
        float val  = (preq >= 0.f) ? preq : 0.01f * preq;
        val *= (1.0f / CPACK);
        g_u[src ^ 1][(size_t)b * D + j] = val;

        float v2 = val * val;
#pragma unroll
        for (int o = 16; o; o >>= 1) v2 += __shfl_down_sync(0xFFFFFFFFu, v2, o);
        if (L == 0) arr_out[b] = v2;
    }
    __syncthreads();
    if (tid < B)
        g_part[src ^ 1][blockIdx.x][tid] = arr_out[tid];
}

// ---------------------------------------------------------------------------
// Final L2 normalize of g_u[0] rows into the external output.
// ---------------------------------------------------------------------------
__global__ void norm_kernel(float* __restrict__ out) {
    const int b = blockIdx.x, tid = threadIdx.x;  // 8 x 256
    __shared__ float red[8];
    __shared__ float s_inv;
    const float* __restrict__ u = &g_u[0][(size_t)b * D];

    float ss = 0.f;
    for (int i = tid; i < D; i += 256) { float v = u[i]; ss = fmaf(v, v, ss); }
#pragma unroll
    for (int o = 16; o; o >>= 1) ss += __shfl_down_sync(0xFFFFFFFFu, ss, o);
    if ((tid & 31) == 0) red[tid >> 5] = ss;
    __syncthreads();
    if (tid == 0) {
        float v = 0.f;
#pragma unroll
        for (int w = 0; w < 8; w++) v += red[w];
        s_inv = 1.0f / fmaxf(sqrtf(v), 1e-12f);
    }
    __syncthreads();
    const float inv = s_inv;
    for (int i = tid; i < D; i += 256) out[b * D + i] = u[i] * inv;
}

// ---------------------------------------------------------------------------
extern "C" void kernel_launch(void* const* d_in, const int* in_sizes, int n_in,
                              void* d_out, int out_size) {
    const float* x  = (const float*)d_in[0];   // (8, 8192)
    const float* M  = (const float*)d_in[1];   // (8192, 8192)
    const float* hs = (const float*)d_in[2];   // (1, 8192) zeros
    float* out = (float*)d_out;                // (8, 8192)

    convert_i8_kernel<<<16384, 256>>>(M);      // M -> pair-fragment-linear s8
    convert_i4_kernel<<<8192, 256>>>();        // s8 -> nibble-packed s4 (32 MB)
    prep_kernel<<<8, 256>>>(x);                // x -> g_u[0], norms, zero g_sums[0]

    // Steps 0..12 on 4-bit M (errors contracted by the attractor);
    // steps 13..15 on full 8-bit M (verified path) to restore precision.
    for (int t = 0; t < 16; ++t) {
        pack_kernel<<<64, 256>>>(t & 1);
        if (t == 0)      iter4_kernel<true><<<NBLK, 512>>>(hs, 0);
        else if (t < 13) iter4_kernel<false><<<NBLK, 512>>>(hs, t & 1);
        else             iter8_kernel<<<NBLK, 1024>>>(hs, t & 1);
    }

    // u_16 lives in g_u[0]; one final normalize
    norm_kernel<<<8, 256>>>(out);
}